// round 4
// baseline (speedup 1.0000x reference)
#include <cuda_runtime.h>

typedef unsigned long long ull;
#define DI __device__ __forceinline__

// ---- packed f32x2 helpers (sm_103a FFMA2 path, PTX-only per SASS_QUICKREF) ----
DI ull pk2(float a, float b){ ull r; asm("mov.b64 %0, {%1,%2};" : "=l"(r) : "f"(a), "f"(b)); return r; }
DI void upk2(ull v, float& a, float& b){ asm("mov.b64 {%0,%1}, %2;" : "=f"(a), "=f"(b) : "l"(v)); }
DI ull ffma2(ull a, ull b, ull c){ ull r; asm("fma.rn.f32x2 %0, %1, %2, %3;" : "=l"(r) : "l"(a), "l"(b), "l"(c)); return r; }
DI ull fmul2(ull a, ull b){ ull r; asm("mul.rn.f32x2 %0, %1, %2;" : "=l"(r) : "l"(a), "l"(b)); return r; }
DI ull fadd2(ull a, ull b){ ull r; asm("add.rn.f32x2 %0, %1, %2;" : "=l"(r) : "l"(a), "l"(b)); return r; }

// ---- problem constants (fixed by setup_inputs: B=2,H=8,T=8192,D=64,W=512) ----
constexpr int T_  = 8192;
constexpr int WIN = 512;
constexpr int TQ  = 128;
constexpr int TK  = 128;
// 1/sqrt(64) * log2(e): softmax done in exp2 domain
#define QSCALE 0.18033688011112042592f

// smem layouts (float strides)
constexpr int SQS = 130;   // sQ[d][q]
constexpr int SKS = 138;   // sK[d][pair-swizzled k]
constexpr int SVS = 68;    // sV[k][pair-swizzled d]
constexpr int SPS = 132;   // sP[q][xor-swizzled k]
constexpr int OFF_Q = 0;
constexpr int OFF_K = OFF_Q + 64 * SQS;    // 8320
constexpr int OFF_V = OFF_K + 64 * SKS;    // 17152
constexpr int OFF_P = OFF_V + 128 * SVS;   // 25856
constexpr int SMEM_FLOATS = OFF_P + 128 * SPS; // 42752
constexpr int SMEM_BYTES  = SMEM_FLOATS * 4;   // 171008

__global__ void __launch_bounds__(256, 1) swa_kernel(
    const float* __restrict__ Qg, const float* __restrict__ Kg,
    const float* __restrict__ Vg, float* __restrict__ Og)
{
    extern __shared__ float sm[];
    float* sQ = sm + OFF_Q;
    float* sK = sm + OFF_K;
    float* sV = sm + OFF_V;
    float* sP = sm + OFF_P;

    const int tid = threadIdx.x;
    const int qb  = blockIdx.x;
    const int bh  = blockIdx.y;
    const int q0  = qb * TQ;
    const long base = (long)bh * T_ * 64;

    // ---- load Q tile once: transpose to sQ[d][q], pre-scale ----
    {
        const float4* g = (const float4*)(Qg + base + (long)q0 * 64);
        #pragma unroll
        for (int r = 0; r < 8; r++) {
            int idx = tid + r * 256;
            int q = idx >> 4, c = (idx & 15) * 4;
            float4 v = g[idx];
            sQ[(c + 0) * SQS + q] = v.x * QSCALE;
            sQ[(c + 1) * SQS + q] = v.y * QSCALE;
            sQ[(c + 2) * SQS + q] = v.z * QSCALE;
            sQ[(c + 3) * SQS + q] = v.w * QSCALE;
        }
    }

    // thread roles
    const int qg = tid >> 4;         // 0..15: query group (8 rows), same in both phases
    const int kg = tid & 15;         // 0..15: key group of 8 (QK phase)
    const int dg = tid & 7;          // 0..7 : d group of 8 (PV phase)
    const int kh = (tid >> 3) & 1;   // k parity (PV phase)

    // swizzled pair-column offsets (conflict-free LDS.64)
    int kcol[4], vcol[4];
    #pragma unroll
    for (int j = 0; j < 4; j++) {
        int kp = kg * 4 + j; kcol[j] = (kp + (kp >> 4)) * 2;
        int vp = dg * 4 + j; vcol[j] = (vp + (vp >> 4)) * 2;
    }
    // P-buffer xor swizzle pieces
    const int pxq = (qg & 1) << 4;                              // row-group bit
    const int pst = (kg * 8) ^ (((kg >> 2) & 3) << 2) ^ pxq;    // store col base

    ull oacc[8][4];
    float mrow[8], lrow[8];
    #pragma unroll
    for (int i = 0; i < 8; i++) {
        mrow[i] = -1e30f; lrow[i] = 0.f;
        #pragma unroll
        for (int j = 0; j < 4; j++) oacc[i][j] = 0ull;
    }

    const int kstart = (q0 - WIN > 0) ? (q0 - WIN) : 0;
    const int kend   = (q0 + TQ + WIN < T_) ? (q0 + TQ + WIN) : T_;

    for (int k0 = kstart; k0 < kend; k0 += TK) {
        __syncthreads();  // prior-iteration sV reads complete before overwrite
        // ---- load K (transposed + pair-swizzled) and V (rows, pair-swizzled) ----
        {
            const float4* gk = (const float4*)(Kg + base + (long)k0 * 64);
            const float4* gv = (const float4*)(Vg + base + (long)k0 * 64);
            #pragma unroll
            for (int r = 0; r < 8; r++) {
                int idx = tid + r * 256;
                int k = idx >> 4, c = (idx & 15) * 4;
                float4 kv = gk[idx];
                int kp  = k >> 1;
                int pos = (kp + (kp >> 4)) * 2 + (k & 1);
                sK[(c + 0) * SKS + pos] = kv.x;
                sK[(c + 1) * SKS + pos] = kv.y;
                sK[(c + 2) * SKS + pos] = kv.z;
                sK[(c + 3) * SKS + pos] = kv.w;
                float4 vv4 = gv[idx];
                int vp0 = c >> 1;
                int p0 = (vp0 + (vp0 >> 4)) * 2;
                int p1 = ((vp0 + 1) + ((vp0 + 1) >> 4)) * 2;
                *(ull*)(sV + k * SVS + p0) = pk2(vv4.x, vv4.y);
                *(ull*)(sV + k * SVS + p1) = pk2(vv4.z, vv4.w);
            }
        }
        __syncthreads();

        // ---- S = Q·K^T : 8q x 8k per thread, packed along k ----
        ull sacc[8][4];
        #pragma unroll
        for (int i = 0; i < 8; i++)
            #pragma unroll
            for (int j = 0; j < 4; j++) sacc[i][j] = 0ull;
        {
            const float* kptr = sK;
            const float* qptr = sQ + qg * 8;
            #pragma unroll 4
            for (int d = 0; d < 64; d++) {
                ull kv[4];
                #pragma unroll
                for (int j = 0; j < 4; j++) kv[j] = *(const ull*)(kptr + kcol[j]);
                #pragma unroll
                for (int ip = 0; ip < 4; ip++) {
                    float2 qp = *(const float2*)(qptr + 2 * ip);
                    ull qa = pk2(qp.x, qp.x);
                    ull qb2 = pk2(qp.y, qp.y);
                    #pragma unroll
                    for (int j = 0; j < 4; j++) {
                        sacc[2 * ip    ][j] = ffma2(qa,  kv[j], sacc[2 * ip    ][j]);
                        sacc[2 * ip + 1][j] = ffma2(qb2, kv[j], sacc[2 * ip + 1][j]);
                    }
                }
                kptr += SKS; qptr += SQS;
            }
        }

        // ---- online softmax (row groups of 16 lanes share a warp half) ----
        const bool maskTile = (k0 - q0 == WIN) || (q0 - k0 == WIN);
        float scarr[8];
        float* sProw = sP + (qg * 8) * SPS;
        #pragma unroll
        for (int i = 0; i < 8; i++) {
            float s[8];
            upk2(sacc[i][0], s[0], s[1]);
            upk2(sacc[i][1], s[2], s[3]);
            upk2(sacc[i][2], s[4], s[5]);
            upk2(sacc[i][3], s[6], s[7]);
            if (maskTile) {
                int qgl = q0 + qg * 8 + i;
                #pragma unroll
                for (int jj = 0; jj < 8; jj++) {
                    int kgl = k0 + kg * 8 + jj;
                    int dlt = qgl - kgl; if (dlt < 0) dlt = -dlt;
                    if (dlt > WIN) s[jj] = -1e30f;
                }
            }
            float mt = fmaxf(fmaxf(fmaxf(s[0], s[1]), fmaxf(s[2], s[3])),
                             fmaxf(fmaxf(s[4], s[5]), fmaxf(s[6], s[7])));
            #pragma unroll
            for (int st = 1; st <= 8; st <<= 1)
                mt = fmaxf(mt, __shfl_xor_sync(0xffffffffu, mt, st));
            float mnew = fmaxf(mrow[i], mt);
            float sc = exp2f(mrow[i] - mnew);
            mrow[i] = mnew;
            scarr[i] = sc;
            float p[8], ls = 0.f;
            #pragma unroll
            for (int jj = 0; jj < 8; jj++) { p[jj] = exp2f(s[jj] - mnew); ls += p[jj]; }
            #pragma unroll
            for (int st = 1; st <= 8; st <<= 1)
                ls += __shfl_xor_sync(0xffffffffu, ls, st);
            lrow[i] = lrow[i] * sc + ls;
            float4 a = make_float4(p[0], p[1], p[2], p[3]);
            float4 b = make_float4(p[4], p[5], p[6], p[7]);
            *(float4*)(sProw + i * SPS + pst)       = a;
            *(float4*)(sProw + i * SPS + (pst ^ 4)) = b;
        }
        // rescale output accumulators
        #pragma unroll
        for (int i = 0; i < 8; i++) {
            ull scp = pk2(scarr[i], scarr[i]);
            #pragma unroll
            for (int j = 0; j < 4; j++) oacc[i][j] = fmul2(oacc[i][j], scp);
        }
        __syncwarp();  // P producers == P consumers' warp

        // ---- O += P·V : 8q x 8d per thread, k split by parity kh ----
        {
            #pragma unroll 2
            for (int kk = 0; kk < 64; kk++) {
                int k = 2 * kk + kh;
                int pcol = k ^ (((k >> 5) & 3) << 2) ^ pxq;
                float pv[8];
                #pragma unroll
                for (int i = 0; i < 8; i++) pv[i] = sProw[i * SPS + pcol];
                ull vv[4];
                const float* vr = sV + k * SVS;
                #pragma unroll
                for (int j = 0; j < 4; j++) vv[j] = *(const ull*)(vr + vcol[j]);
                #pragma unroll
                for (int i = 0; i < 8; i++) {
                    ull pp = pk2(pv[i], pv[i]);
                    #pragma unroll
                    for (int j = 0; j < 4; j++) oacc[i][j] = ffma2(pp, vv[j], oacc[i][j]);
                }
            }
        }
    }

    // ---- epilogue: combine kh halves, normalize, write ----
    #pragma unroll
    for (int i = 0; i < 8; i++)
        #pragma unroll
        for (int j = 0; j < 4; j++)
            oacc[i][j] = fadd2(oacc[i][j], __shfl_xor_sync(0xffffffffu, oacc[i][j], 8));

    const int i0 = kh * 4;  // kh=0 writes rows 0..3, kh=1 rows 4..7
    #pragma unroll
    for (int ii = 0; ii < 4; ii++) {
        int i = i0 + ii;
        float inv = 1.0f / lrow[i];
        float o[8];
        upk2(oacc[i][0], o[0], o[1]);
        upk2(oacc[i][1], o[2], o[3]);
        upk2(oacc[i][2], o[4], o[5]);
        upk2(oacc[i][3], o[6], o[7]);
        float* dst = Og + base + (long)(q0 + qg * 8 + i) * 64 + dg * 8;
        float4 w0 = make_float4(o[0] * inv, o[1] * inv, o[2] * inv, o[3] * inv);
        float4 w1 = make_float4(o[4] * inv, o[5] * inv, o[6] * inv, o[7] * inv);
        *(float4*)(dst)     = w0;
        *(float4*)(dst + 4) = w1;
    }
}

extern "C" void kernel_launch(void* const* d_in, const int* in_sizes, int n_in,
                              void* d_out, int out_size)
{
    const float* Q = (const float*)d_in[0];
    const float* K = (const float*)d_in[1];
    const float* V = (const float*)d_in[2];
    float* O = (float*)d_out;

    static bool attr_set = false;
    if (!attr_set) {
        cudaFuncSetAttribute(swa_kernel, cudaFuncAttributeMaxDynamicSharedMemorySize,
                             SMEM_BYTES);
        attr_set = true;
    }
    dim3 grid(T_ / TQ, 16);  // 64 q-blocks x (B*H)=16
    swa_kernel<<<grid, 256, SMEM_BYTES>>>(Q, K, V, O);
}